// round 5
// baseline (speedup 1.0000x reference)
#include <cuda_runtime.h>
#include <cuda_bf16.h>
#include <cstdint>

#define NB 32768
#define ND 512
#define NK 8192
#define CAP 64
#define MARGIN_S 4e-4f

// ---------------- device scratch ----------------
__device__ float g_znorm[NB];
__device__ float g_wnorm[NK];
__device__ int   g_bestidx[NB];
__device__ float g_partials[NB];
__device__ unsigned short g_zb[NB * ND];   // bf16 copies
__device__ unsigned short g_wb[NK * ND];
__device__ int g_cnt[NB];
__device__ int g_cand[NB * CAP];

// ---------------- helpers ----------------
__device__ __forceinline__ uint32_t smem_u32(const void* p) {
    uint32_t a;
    asm("{ .reg .u64 t; cvta.to.shared.u64 t, %1; cvt.u32.u64 %0, t; }" : "=r"(a) : "l"(p));
    return a;
}
__device__ __forceinline__ void cp16(uint32_t s, const void* g) {
    asm volatile("cp.async.cg.shared.global [%0], [%1], 16;" :: "r"(s), "l"(g));
}
__device__ __forceinline__ void cp_commit() { asm volatile("cp.async.commit_group;"); }
template <int N>
__device__ __forceinline__ void cp_wait() { asm volatile("cp.async.wait_group %0;" :: "n"(N)); }

__device__ __forceinline__ void ldmA(uint32_t* f, uint32_t addr) {
    asm volatile("ldmatrix.sync.aligned.m8n8.x4.shared.b16 {%0,%1,%2,%3}, [%4];"
                 : "=r"(f[0]), "=r"(f[1]), "=r"(f[2]), "=r"(f[3]) : "r"(addr));
}
__device__ __forceinline__ void ldmB(uint32_t* f, uint32_t addr) {
    asm volatile("ldmatrix.sync.aligned.m8n8.x2.shared.b16 {%0,%1}, [%2];"
                 : "=r"(f[0]), "=r"(f[1]) : "r"(addr));
}
__device__ __forceinline__ void mma16816(float* c, const uint32_t* a, const uint32_t* b) {
    asm volatile("mma.sync.aligned.m16n8k16.row.col.f32.bf16.bf16.f32 "
                 "{%0,%1,%2,%3}, {%4,%5,%6,%7}, {%8,%9}, {%0,%1,%2,%3};"
                 : "+f"(c[0]), "+f"(c[1]), "+f"(c[2]), "+f"(c[3])
                 : "r"(a[0]), "r"(a[1]), "r"(a[2]), "r"(a[3]), "r"(b[0]), "r"(b[1]));
}
__device__ __forceinline__ unsigned fkey(float x) {
    unsigned u = __float_as_uint(x);
    return (u & 0x80000000u) ? ~u : (u | 0x80000000u);
}
__device__ __forceinline__ float fdec(unsigned k) {
    return (k & 0x80000000u) ? __uint_as_float(k & 0x7fffffffu) : __uint_as_float(~k);
}

// ---------------- row norms (exact, sequential) + cnt zero ----------------
__global__ void rownorm_z(const float* __restrict__ x) {
    int r = blockIdx.x * blockDim.x + threadIdx.x;
    if (r >= NB) return;
    const float4* p = reinterpret_cast<const float4*>(x + (size_t)r * ND);
    float acc = 0.f;
#pragma unroll 4
    for (int i = 0; i < ND / 4; i++) {
        float4 v = __ldg(p + i);
        acc = __fadd_rn(acc, __fmul_rn(v.x, v.x));
        acc = __fadd_rn(acc, __fmul_rn(v.y, v.y));
        acc = __fadd_rn(acc, __fmul_rn(v.z, v.z));
        acc = __fadd_rn(acc, __fmul_rn(v.w, v.w));
    }
    g_znorm[r] = acc;
    g_cnt[r] = 0;
}
__global__ void rownorm_w(const float* __restrict__ x) {
    int r = blockIdx.x * blockDim.x + threadIdx.x;
    if (r >= NK) return;
    const float4* p = reinterpret_cast<const float4*>(x + (size_t)r * ND);
    float acc = 0.f;
#pragma unroll 4
    for (int i = 0; i < ND / 4; i++) {
        float4 v = __ldg(p + i);
        acc = __fadd_rn(acc, __fmul_rn(v.x, v.x));
        acc = __fadd_rn(acc, __fmul_rn(v.y, v.y));
        acc = __fadd_rn(acc, __fmul_rn(v.z, v.z));
        acc = __fadd_rn(acc, __fmul_rn(v.w, v.w));
    }
    g_wnorm[r] = acc;
}

// ---------------- fp32 -> bf16 convert ----------------
__global__ void conv_bf16(const float* __restrict__ src, unsigned short* dst, int n8) {
    int i = blockIdx.x * blockDim.x + threadIdx.x;
    if (i >= n8) return;
    const float4* s = reinterpret_cast<const float4*>(src) + i * 2;
    float4 a = __ldg(s), b = __ldg(s + 1);
    uint4 o;
    o.x = (uint32_t)__bfloat16_as_ushort(__float2bfloat16_rn(a.x)) |
          ((uint32_t)__bfloat16_as_ushort(__float2bfloat16_rn(a.y)) << 16);
    o.y = (uint32_t)__bfloat16_as_ushort(__float2bfloat16_rn(a.z)) |
          ((uint32_t)__bfloat16_as_ushort(__float2bfloat16_rn(a.w)) << 16);
    o.z = (uint32_t)__bfloat16_as_ushort(__float2bfloat16_rn(b.x)) |
          ((uint32_t)__bfloat16_as_ushort(__float2bfloat16_rn(b.y)) << 16);
    o.w = (uint32_t)__bfloat16_as_ushort(__float2bfloat16_rn(b.z)) |
          ((uint32_t)__bfloat16_as_ushort(__float2bfloat16_rn(b.w)) << 16);
    reinterpret_cast<uint4*>(dst)[i] = o;
}

// ---------------- HMMA filter v2 ----------------
// A (128 z-rows x 512) resident in smem, XOR-swizzled, loaded once.
// B streamed in BK=64 column blocks through a 4-stage cp.async ring.
// 512 steps total (64 n-tiles x 8 k-blocks), ONE __syncthreads per step.
#define APITCH 1024            // bytes per A row (512 bf16), XOR swizzle
#define A_BYTES (128 * APITCH) // 131072
#define BPITCH 144             // 128B data + 16B pad (conflict-free)
#define BSTAGE (128 * BPITCH)  // 18432
#define NSTAGES 4
#define SMEM_DYN (A_BYTES + NSTAGES * BSTAGE)  // 204800

__global__ __launch_bounds__(256, 1) void mma_filter() {
    extern __shared__ char dsm[];
    __shared__ unsigned rmax[128];

    char* sA = dsm;
    char* sB = dsm + A_BYTES;

    int tid = threadIdx.x, lid = tid & 31, wid = tid >> 5;
    int wm = wid >> 2, wn = wid & 3;     // warp grid 2 (m) x 4 (n)
    int m0 = blockIdx.x * 128;

    if (tid < 128) rmax[tid] = 0u;

    uint32_t aBase = smem_u32(sA);
    uint32_t bBase = smem_u32(sB);

    // ---- issue resident-A load (one commit group) ----
    {
        int r = tid >> 1, h = tid & 1;
        const unsigned short* gsrc = g_zb + (size_t)(m0 + r) * ND + h * 256;
        uint32_t rowb = aBase + r * APITCH;
        uint32_t sw = (uint32_t)((r & 7) << 4);
#pragma unroll
        for (int q = 0; q < 32; q++) {
            uint32_t cb = (uint32_t)((h * 32 + q) * 16);
            cp16(rowb + (cb ^ sw), gsrc + q * 8);
        }
    }
    cp_commit();

    // ---- B stage loader ----
    // stage covers rows n0..n0+127, cols kb*64..kb*64+63 of W (bf16)
    int br = tid >> 1, bc0 = (tid & 1) * 4;   // 4 x 16B chunks per thread
    auto issueB = [&](int step) {
        int ntile = step >> 3, kb = step & 7;
        char* buf = sB + (step & (NSTAGES - 1)) * BSTAGE;
        uint32_t bb = smem_u32(buf) + br * BPITCH;
        const unsigned short* gsrc =
            g_wb + (size_t)(ntile * 128 + br) * ND + kb * 64 + bc0 * 8;
#pragma unroll
        for (int q = 0; q < 4; q++)
            cp16(bb + (bc0 + q) * 16, gsrc + q * 8);
        cp_commit();
    };

    // prologue: stages 0..2
    issueB(0); issueB(1); issueB(2);

    // ldmatrix lane addressing
    int lt = lid >> 3, l8 = lid & 7;
    int a_row = wm * 64 + (lt & 1) * 8 + l8;      // + mt*16
    uint32_t a_sw = (uint32_t)(l8 << 4);
    int a_colb0 = (lt >> 1) * 16;                 // bytes, + k*2
    int b_row = wn * 32 + l8;                     // + nt*8
    int b_colb0 = (lt & 1) * 16;                  // bytes

    int g = lid >> 2, tc = (lid & 3) * 2;

    float acc[4][4][4];

    for (int s = 0; s < 512; s++) {
        int ntile = s >> 3, kb = s & 7;
        cp_wait<2>();          // stage s (and A, at s=0) arrived
        __syncthreads();       // data visible to all; prev-step buffer reusable
        if (s + 3 < 512) issueB(s + 3);

        if (kb == 0) {
#pragma unroll
            for (int mt = 0; mt < 4; mt++)
#pragma unroll
                for (int nt = 0; nt < 4; nt++)
#pragma unroll
                    for (int q = 0; q < 4; q++) acc[mt][nt][q] = 0.f;
        }

        uint32_t bCur = bBase + (s & (NSTAGES - 1)) * BSTAGE;
#pragma unroll
        for (int ks = 0; ks < 4; ks++) {
            uint32_t af[4][4], bf[4][2];
            uint32_t acolb = (uint32_t)(kb * 128 + ks * 32 + a_colb0);
#pragma unroll
            for (int mt = 0; mt < 4; mt++)
                ldmA(af[mt], aBase + (a_row + mt * 16) * APITCH + (acolb ^ a_sw));
#pragma unroll
            for (int nt = 0; nt < 4; nt++)
                ldmB(bf[nt], bCur + (b_row + nt * 8) * BPITCH + ks * 32 + b_colb0);
#pragma unroll
            for (int mt = 0; mt < 4; mt++)
#pragma unroll
                for (int nt = 0; nt < 4; nt++)
                    mma16816(acc[mt][nt], af[mt], bf[nt]);
        }

        if (kb == 7) {
            int n0 = ntile * 128;
#pragma unroll
            for (int mt = 0; mt < 4; mt++) {
#pragma unroll
                for (int h = 0; h < 2; h++) {
                    float m8 = -1e30f;
#pragma unroll
                    for (int nt = 0; nt < 4; nt++)
                        m8 = fmaxf(m8, fmaxf(acc[mt][nt][h * 2], acc[mt][nt][h * 2 + 1]));
                    int r = wm * 64 + mt * 16 + h * 8 + g;
                    unsigned old = atomicMax(&rmax[r], fkey(m8));
                    float cur = fmaxf(m8, fdec(old));
                    float th = cur - MARGIN_S;
                    int grow = m0 + r;
#pragma unroll
                    for (int nt = 0; nt < 4; nt++)
#pragma unroll
                        for (int cc = 0; cc < 2; cc++) {
                            float v = acc[mt][nt][h * 2 + cc];
                            if (v >= th) {
                                int slot = atomicAdd(&g_cnt[grow], 1);
                                if (slot < CAP)
                                    g_cand[grow * CAP + slot] = n0 + wn * 32 + nt * 8 + tc + cc;
                            }
                        }
                }
            }
        }
    }
}

// ---------------- exact rescoring (reference rounding) ----------------
__global__ __launch_bounds__(256) void exact_pass(const float* __restrict__ z,
                                                  const float* __restrict__ W) {
    __shared__ float zs[8][ND];
    int wrp = threadIdx.x >> 5, lid = threadIdx.x & 31;
    int row = blockIdx.x * 8 + wrp;
    if (row >= NB) return;

    float4* zd = reinterpret_cast<float4*>(zs[wrp]);
    const float4* zsrc = reinterpret_cast<const float4*>(z + (size_t)row * ND);
#pragma unroll
    for (int i = 0; i < ND / 4 / 32; i++) zd[lid + i * 32] = __ldg(zsrc + lid + i * 32);
    __syncwarp();

    int cnt = g_cnt[row];
    float zn = g_znorm[row];
    float best = __int_as_float(0x7f800000);
    int bi = 0x7fffffff;

    if (cnt <= CAP) {
        for (int s = lid; s < cnt; s += 32) {
            int k = g_cand[row * CAP + s];
            const float4* wr = reinterpret_cast<const float4*>(W + (size_t)k * ND);
            float acc = 0.f;
#pragma unroll 4
            for (int d = 0; d < ND / 4; d++) {
                float4 wv = __ldg(wr + d);
                float4 zv = zd[d];
                acc = __fmaf_rn(zv.x, wv.x, acc);
                acc = __fmaf_rn(zv.y, wv.y, acc);
                acc = __fmaf_rn(zv.z, wv.z, acc);
                acc = __fmaf_rn(zv.w, wv.w, acc);
            }
            float d2 = __fsub_rn(__fadd_rn(zn, g_wnorm[k]), __fmul_rn(2.0f, acc));
            if (d2 < best || (d2 == best && k < bi)) { best = d2; bi = k; }
        }
    } else {
        for (int k = lid; k < NK; k += 32) {
            const float4* wr = reinterpret_cast<const float4*>(W + (size_t)k * ND);
            float acc = 0.f;
#pragma unroll 4
            for (int d = 0; d < ND / 4; d++) {
                float4 wv = __ldg(wr + d);
                float4 zv = zd[d];
                acc = __fmaf_rn(zv.x, wv.x, acc);
                acc = __fmaf_rn(zv.y, wv.y, acc);
                acc = __fmaf_rn(zv.z, wv.z, acc);
                acc = __fmaf_rn(zv.w, wv.w, acc);
            }
            float d2 = __fsub_rn(__fadd_rn(zn, g_wnorm[k]), __fmul_rn(2.0f, acc));
            if (d2 < best || (d2 == best && k < bi)) { best = d2; bi = k; }
        }
    }
#pragma unroll
    for (int off = 16; off > 0; off >>= 1) {
        float ov = __shfl_down_sync(0xffffffffu, best, off);
        int oi = __shfl_down_sync(0xffffffffu, bi, off);
        if (ov < best || (ov == best && oi < bi)) { best = ov; bi = oi; }
    }
    if (lid == 0) g_bestidx[row] = bi;
}

// ---------------- gather + loss ----------------
__global__ void gather_out(const float* __restrict__ z, const float* __restrict__ W,
                           float* __restrict__ out, int out_size) {
    int b = blockIdx.x, t = threadIdx.x;
    int idx = g_bestidx[b];
    const float* wr = W + (size_t)idx * ND;
    const float* zr = z + (size_t)b * ND;
    float s = 0.f;
#pragma unroll
    for (int i = 0; i < ND / 128; i++) {
        int j = t + i * 128;
        float wv = wr[j], zv = zr[j];
        float diff = __fsub_rn(wv, zv);
        out[(size_t)b * ND + j] = __fadd_rn(zv, diff);
        s = __fmaf_rn(diff, diff, s);
    }
    __shared__ float sm[128];
    sm[t] = s;
    __syncthreads();
    for (int o = 64; o > 0; o >>= 1) {
        if (t < o) sm[t] += sm[t + o];
        __syncthreads();
    }
    if (t == 0) {
        g_partials[b] = sm[0];
        size_t off = (size_t)NB * ND + b;
        if (off < (size_t)out_size) out[off] = (float)idx;
    }
}
__global__ void loss_reduce(float* __restrict__ out, int out_size) {
    __shared__ float sm[256];
    int t = threadIdx.x;
    float s = 0.f;
    for (int i = t; i < NB; i += 256) s += g_partials[i];
    sm[t] = s;
    __syncthreads();
    for (int o = 128; o > 0; o >>= 1) {
        if (t < o) sm[t] += sm[t + o];
        __syncthreads();
    }
    if (t == 0) {
        size_t off = (size_t)NB * ND + NB;
        if (off < (size_t)out_size)
            out[off] = 1.25f * (sm[0] / (float)((size_t)NB * ND));
    }
}

// ---------------- launch ----------------
extern "C" void kernel_launch(void* const* d_in, const int* in_sizes, int n_in,
                              void* d_out, int out_size) {
    const float* z = (const float*)d_in[0];
    const float* W = (const float*)d_in[1];
    float* out = (float*)d_out;

    static int smem_set = 0;
    if (!smem_set) {
        cudaFuncSetAttribute(mma_filter, cudaFuncAttributeMaxDynamicSharedMemorySize, SMEM_DYN);
        smem_set = 1;
    }

    unsigned short* zb_ptr = nullptr;
    unsigned short* wb_ptr = nullptr;
    cudaGetSymbolAddress((void**)&zb_ptr, g_zb);
    cudaGetSymbolAddress((void**)&wb_ptr, g_wb);

    rownorm_z<<<NB / 128, 128>>>(z);
    rownorm_w<<<NK / 128, 128>>>(W);
    conv_bf16<<<(NB * ND / 8 + 255) / 256, 256>>>(z, zb_ptr, NB * ND / 8);
    conv_bf16<<<(NK * ND / 8 + 255) / 256, 256>>>(W, wb_ptr, NK * ND / 8);
    mma_filter<<<NB / 128, 256, SMEM_DYN>>>();
    exact_pass<<<NB / 8, 256>>>(z, W);
    gather_out<<<NB, 128>>>(z, W, out, out_size);
    loss_reduce<<<1, 256>>>(out, out_size);
}

// round 6
// speedup vs baseline: 1.0270x; 1.0270x over previous
#include <cuda_runtime.h>
#include <cuda_bf16.h>
#include <cstdint>

#define NB 32768
#define ND 512
#define NK 8192
#define CAP 64
#define MARGIN_S 4e-4f

// ---------------- device scratch ----------------
__device__ float g_znorm[NB];
__device__ float g_wnorm[NK];
__device__ int   g_bestidx[NB];
__device__ float g_partials[NB];
__device__ unsigned short g_zb[NB * ND];   // bf16 copies
__device__ unsigned short g_wb[NK * ND];
__device__ int g_cnt[NB];
__device__ int g_cand[NB * CAP];

// ---------------- helpers ----------------
__device__ __forceinline__ uint32_t smem_u32(const void* p) {
    uint32_t a;
    asm("{ .reg .u64 t; cvta.to.shared.u64 t, %1; cvt.u32.u64 %0, t; }" : "=r"(a) : "l"(p));
    return a;
}
__device__ __forceinline__ void cp16(uint32_t s, const void* g) {
    asm volatile("cp.async.cg.shared.global [%0], [%1], 16;" :: "r"(s), "l"(g));
}
__device__ __forceinline__ void cp_commit() { asm volatile("cp.async.commit_group;"); }
template <int N>
__device__ __forceinline__ void cp_wait() { asm volatile("cp.async.wait_group %0;" :: "n"(N)); }

__device__ __forceinline__ void ldmA(uint32_t* f, uint32_t addr) {
    asm volatile("ldmatrix.sync.aligned.m8n8.x4.shared.b16 {%0,%1,%2,%3}, [%4];"
                 : "=r"(f[0]), "=r"(f[1]), "=r"(f[2]), "=r"(f[3]) : "r"(addr));
}
__device__ __forceinline__ void ldmB(uint32_t* f, uint32_t addr) {
    asm volatile("ldmatrix.sync.aligned.m8n8.x2.shared.b16 {%0,%1}, [%2];"
                 : "=r"(f[0]), "=r"(f[1]) : "r"(addr));
}
__device__ __forceinline__ void mma16816(float* c, const uint32_t* a, const uint32_t* b) {
    asm volatile("mma.sync.aligned.m16n8k16.row.col.f32.bf16.bf16.f32 "
                 "{%0,%1,%2,%3}, {%4,%5,%6,%7}, {%8,%9}, {%0,%1,%2,%3};"
                 : "+f"(c[0]), "+f"(c[1]), "+f"(c[2]), "+f"(c[3])
                 : "r"(a[0]), "r"(a[1]), "r"(a[2]), "r"(a[3]), "r"(b[0]), "r"(b[1]));
}
__device__ __forceinline__ unsigned fkey(float x) {
    unsigned u = __float_as_uint(x);
    return (u & 0x80000000u) ? ~u : (u | 0x80000000u);
}
__device__ __forceinline__ float fdec(unsigned k) {
    return (k & 0x80000000u) ? __uint_as_float(k & 0x7fffffffu) : __uint_as_float(~k);
}

// ---------------- row norms (exact, sequential) + cnt zero ----------------
__global__ void rownorm_z(const float* __restrict__ x) {
    int r = blockIdx.x * blockDim.x + threadIdx.x;
    if (r >= NB) return;
    const float4* p = reinterpret_cast<const float4*>(x + (size_t)r * ND);
    float acc = 0.f;
#pragma unroll 4
    for (int i = 0; i < ND / 4; i++) {
        float4 v = __ldg(p + i);
        acc = __fadd_rn(acc, __fmul_rn(v.x, v.x));
        acc = __fadd_rn(acc, __fmul_rn(v.y, v.y));
        acc = __fadd_rn(acc, __fmul_rn(v.z, v.z));
        acc = __fadd_rn(acc, __fmul_rn(v.w, v.w));
    }
    g_znorm[r] = acc;
    g_cnt[r] = 0;
}
__global__ void rownorm_w(const float* __restrict__ x) {
    int r = blockIdx.x * blockDim.x + threadIdx.x;
    if (r >= NK) return;
    const float4* p = reinterpret_cast<const float4*>(x + (size_t)r * ND);
    float acc = 0.f;
#pragma unroll 4
    for (int i = 0; i < ND / 4; i++) {
        float4 v = __ldg(p + i);
        acc = __fadd_rn(acc, __fmul_rn(v.x, v.x));
        acc = __fadd_rn(acc, __fmul_rn(v.y, v.y));
        acc = __fadd_rn(acc, __fmul_rn(v.z, v.z));
        acc = __fadd_rn(acc, __fmul_rn(v.w, v.w));
    }
    g_wnorm[r] = acc;
}

// ---------------- fp32 -> bf16 convert ----------------
__global__ void conv_bf16(const float* __restrict__ src, unsigned short* dst, int n8) {
    int i = blockIdx.x * blockDim.x + threadIdx.x;
    if (i >= n8) return;
    const float4* s = reinterpret_cast<const float4*>(src) + i * 2;
    float4 a = __ldg(s), b = __ldg(s + 1);
    uint4 o;
    o.x = (uint32_t)__bfloat16_as_ushort(__float2bfloat16_rn(a.x)) |
          ((uint32_t)__bfloat16_as_ushort(__float2bfloat16_rn(a.y)) << 16);
    o.y = (uint32_t)__bfloat16_as_ushort(__float2bfloat16_rn(a.z)) |
          ((uint32_t)__bfloat16_as_ushort(__float2bfloat16_rn(a.w)) << 16);
    o.z = (uint32_t)__bfloat16_as_ushort(__float2bfloat16_rn(b.x)) |
          ((uint32_t)__bfloat16_as_ushort(__float2bfloat16_rn(b.y)) << 16);
    o.w = (uint32_t)__bfloat16_as_ushort(__float2bfloat16_rn(b.z)) |
          ((uint32_t)__bfloat16_as_ushort(__float2bfloat16_rn(b.w)) << 16);
    reinterpret_cast<uint4*>(dst)[i] = o;
}

// ---------------- HMMA filter v3 ----------------
// occ=2 (key lesson from r5), BK=64, 3-stage A+B ring, ONE sync per step.
// 512 steps/CTA (64 ntiles x 8 kb), 64 HMMA/warp between barriers.
#define SPITCH 144                 // 128B row data + 16B pad (conflict-free)
#define HCHUNK (128 * SPITCH)      // 18432: one 128x64 bf16 tile
#define STAGEB (2 * HCHUNK)        // A chunk + B chunk
#define NST 3
#define SMEM_DYN (NST * STAGEB)    // 110592

__global__ __launch_bounds__(256, 2) void mma_filter() {
    extern __shared__ char dsm[];
    __shared__ unsigned rmax[128];

    int tid = threadIdx.x, lid = tid & 31, wid = tid >> 5;
    int wm = wid >> 2, wn = wid & 3;     // warp grid 2 (m) x 4 (n)
    int m0 = blockIdx.x * 128;

    if (tid < 128) rmax[tid] = 0u;
    __syncthreads();

    uint32_t base = smem_u32(dsm);

    // per-thread loader coords: row = tid>>1, half = tid&1 (4 x 16B each of A,B)
    int lr = tid >> 1, lh = (tid & 1) * 4;

    auto issue = [&](int step, int buf) {
        int ntile = step >> 3, kb = step & 7;
        uint32_t sa = base + buf * STAGEB + lr * SPITCH + lh * 16;
        uint32_t sbuf = sa + HCHUNK;
        const unsigned short* ga = g_zb + (size_t)(m0 + lr) * ND + kb * 64 + lh * 8;
        const unsigned short* gb = g_wb + (size_t)(ntile * 128 + lr) * ND + kb * 64 + lh * 8;
#pragma unroll
        for (int q = 0; q < 4; q++) cp16(sa + q * 16, ga + q * 8);
#pragma unroll
        for (int q = 0; q < 4; q++) cp16(sbuf + q * 16, gb + q * 8);
        cp_commit();
    };

    issue(0, 0);
    issue(1, 1);

    // ldmatrix lane addressing
    int lt = lid >> 3, l8 = lid & 7;
    int a_row = wm * 64 + (lt & 1) * 8 + l8;        // + mt*16
    int a_colb = (lt >> 1) * 16;                    // + ks*32
    int b_row = wn * 32 + l8;                       // + nt*8
    int b_colb = (lt & 1) * 16;                     // + ks*32

    int g = lid >> 2, tc = (lid & 3) * 2;

    float acc[4][4][4];
    int st_c = 0, st_i = 2;

    for (int s = 0; s < 512; s++) {
        if (s < 510) cp_wait<1>(); else cp_wait<0>();
        __syncthreads();                       // step-s data visible; prior reads done
        if (s + 2 < 512) {
            issue(s + 2, st_i);
            st_i = (st_i == NST - 1) ? 0 : st_i + 1;
        }

        int kb = s & 7;
        if (kb == 0) {
#pragma unroll
            for (int mt = 0; mt < 4; mt++)
#pragma unroll
                for (int nt = 0; nt < 4; nt++)
#pragma unroll
                    for (int q = 0; q < 4; q++) acc[mt][nt][q] = 0.f;
        }

        uint32_t aCur = base + st_c * STAGEB;
        uint32_t bCur = aCur + HCHUNK;
        st_c = (st_c == NST - 1) ? 0 : st_c + 1;

#pragma unroll
        for (int ks = 0; ks < 4; ks++) {
            uint32_t af[4][4], bf[4][2];
#pragma unroll
            for (int mt = 0; mt < 4; mt++)
                ldmA(af[mt], aCur + (a_row + mt * 16) * SPITCH + ks * 32 + a_colb);
#pragma unroll
            for (int nt = 0; nt < 4; nt++)
                ldmB(bf[nt], bCur + (b_row + nt * 8) * SPITCH + ks * 32 + b_colb);
#pragma unroll
            for (int mt = 0; mt < 4; mt++)
#pragma unroll
                for (int nt = 0; nt < 4; nt++)
                    mma16816(acc[mt][nt], af[mt], bf[nt]);
        }

        if (kb == 7) {
            int n0 = (s >> 3) * 128;
#pragma unroll
            for (int mt = 0; mt < 4; mt++) {
#pragma unroll
                for (int h = 0; h < 2; h++) {
                    float m8 = -1e30f;
#pragma unroll
                    for (int nt = 0; nt < 4; nt++)
                        m8 = fmaxf(m8, fmaxf(acc[mt][nt][h * 2], acc[mt][nt][h * 2 + 1]));
                    int r = wm * 64 + mt * 16 + h * 8 + g;
                    unsigned old = atomicMax(&rmax[r], fkey(m8));
                    float cur = fmaxf(m8, fdec(old));   // fdec(0)=NaN -> picks m8
                    float th = cur - MARGIN_S;
                    int grow = m0 + r;
#pragma unroll
                    for (int nt = 0; nt < 4; nt++)
#pragma unroll
                        for (int cc = 0; cc < 2; cc++) {
                            float v = acc[mt][nt][h * 2 + cc];
                            if (v >= th) {
                                int slot = atomicAdd(&g_cnt[grow], 1);
                                if (slot < CAP)
                                    g_cand[grow * CAP + slot] = n0 + wn * 32 + nt * 8 + tc + cc;
                            }
                        }
                }
            }
        }
    }
}

// ---------------- exact rescoring (reference rounding) ----------------
__global__ __launch_bounds__(256) void exact_pass(const float* __restrict__ z,
                                                  const float* __restrict__ W) {
    __shared__ float zs[8][ND];
    int wrp = threadIdx.x >> 5, lid = threadIdx.x & 31;
    int row = blockIdx.x * 8 + wrp;
    if (row >= NB) return;

    float4* zd = reinterpret_cast<float4*>(zs[wrp]);
    const float4* zsrc = reinterpret_cast<const float4*>(z + (size_t)row * ND);
#pragma unroll
    for (int i = 0; i < ND / 4 / 32; i++) zd[lid + i * 32] = __ldg(zsrc + lid + i * 32);
    __syncwarp();

    int cnt = g_cnt[row];
    float zn = g_znorm[row];
    float best = __int_as_float(0x7f800000);
    int bi = 0x7fffffff;

    if (cnt <= CAP) {
        for (int s = lid; s < cnt; s += 32) {
            int k = g_cand[row * CAP + s];
            const float4* wr = reinterpret_cast<const float4*>(W + (size_t)k * ND);
            float acc = 0.f;
#pragma unroll 4
            for (int d = 0; d < ND / 4; d++) {
                float4 wv = __ldg(wr + d);
                float4 zv = zd[d];
                acc = __fmaf_rn(zv.x, wv.x, acc);
                acc = __fmaf_rn(zv.y, wv.y, acc);
                acc = __fmaf_rn(zv.z, wv.z, acc);
                acc = __fmaf_rn(zv.w, wv.w, acc);
            }
            float d2 = __fsub_rn(__fadd_rn(zn, g_wnorm[k]), __fmul_rn(2.0f, acc));
            if (d2 < best || (d2 == best && k < bi)) { best = d2; bi = k; }
        }
    } else {
        for (int k = lid; k < NK; k += 32) {
            const float4* wr = reinterpret_cast<const float4*>(W + (size_t)k * ND);
            float acc = 0.f;
#pragma unroll 4
            for (int d = 0; d < ND / 4; d++) {
                float4 wv = __ldg(wr + d);
                float4 zv = zd[d];
                acc = __fmaf_rn(zv.x, wv.x, acc);
                acc = __fmaf_rn(zv.y, wv.y, acc);
                acc = __fmaf_rn(zv.z, wv.z, acc);
                acc = __fmaf_rn(zv.w, wv.w, acc);
            }
            float d2 = __fsub_rn(__fadd_rn(zn, g_wnorm[k]), __fmul_rn(2.0f, acc));
            if (d2 < best || (d2 == best && k < bi)) { best = d2; bi = k; }
        }
    }
#pragma unroll
    for (int off = 16; off > 0; off >>= 1) {
        float ov = __shfl_down_sync(0xffffffffu, best, off);
        int oi = __shfl_down_sync(0xffffffffu, bi, off);
        if (ov < best || (ov == best && oi < bi)) { best = ov; bi = oi; }
    }
    if (lid == 0) g_bestidx[row] = bi;
}

// ---------------- gather + loss ----------------
__global__ void gather_out(const float* __restrict__ z, const float* __restrict__ W,
                           float* __restrict__ out, int out_size) {
    int b = blockIdx.x, t = threadIdx.x;
    int idx = g_bestidx[b];
    const float* wr = W + (size_t)idx * ND;
    const float* zr = z + (size_t)b * ND;
    float s = 0.f;
#pragma unroll
    for (int i = 0; i < ND / 128; i++) {
        int j = t + i * 128;
        float wv = wr[j], zv = zr[j];
        float diff = __fsub_rn(wv, zv);
        out[(size_t)b * ND + j] = __fadd_rn(zv, diff);
        s = __fmaf_rn(diff, diff, s);
    }
    __shared__ float sm[128];
    sm[t] = s;
    __syncthreads();
    for (int o = 64; o > 0; o >>= 1) {
        if (t < o) sm[t] += sm[t + o];
        __syncthreads();
    }
    if (t == 0) {
        g_partials[b] = sm[0];
        size_t off = (size_t)NB * ND + b;
        if (off < (size_t)out_size) out[off] = (float)idx;
    }
}
__global__ void loss_reduce(float* __restrict__ out, int out_size) {
    __shared__ float sm[256];
    int t = threadIdx.x;
    float s = 0.f;
    for (int i = t; i < NB; i += 256) s += g_partials[i];
    sm[t] = s;
    __syncthreads();
    for (int o = 128; o > 0; o >>= 1) {
        if (t < o) sm[t] += sm[t + o];
        __syncthreads();
    }
    if (t == 0) {
        size_t off = (size_t)NB * ND + NB;
        if (off < (size_t)out_size)
            out[off] = 1.25f * (sm[0] / (float)((size_t)NB * ND));
    }
}

// ---------------- launch ----------------
extern "C" void kernel_launch(void* const* d_in, const int* in_sizes, int n_in,
                              void* d_out, int out_size) {
    const float* z = (const float*)d_in[0];
    const float* W = (const float*)d_in[1];
    float* out = (float*)d_out;

    static int smem_set = 0;
    if (!smem_set) {
        cudaFuncSetAttribute(mma_filter, cudaFuncAttributeMaxDynamicSharedMemorySize, SMEM_DYN);
        smem_set = 1;
    }

    unsigned short* zb_ptr = nullptr;
    unsigned short* wb_ptr = nullptr;
    cudaGetSymbolAddress((void**)&zb_ptr, g_zb);
    cudaGetSymbolAddress((void**)&wb_ptr, g_wb);

    rownorm_z<<<NB / 128, 128>>>(z);
    rownorm_w<<<NK / 128, 128>>>(W);
    conv_bf16<<<(NB * ND / 8 + 255) / 256, 256>>>(z, zb_ptr, NB * ND / 8);
    conv_bf16<<<(NK * ND / 8 + 255) / 256, 256>>>(W, wb_ptr, NK * ND / 8);
    mma_filter<<<NB / 128, 256, SMEM_DYN>>>();
    exact_pass<<<NB / 8, 256>>>(z, W);
    gather_out<<<NB, 128>>>(z, W, out, out_size);
    loss_reduce<<<1, 256>>>(out, out_size);
}